// round 9
// baseline (speedup 1.0000x reference)
#include <cuda_runtime.h>
#include <cuda_bf16.h>

// Two-phase AngularDescriptor via moment expansion.
//   q[i,d,l] = 0.5 * ( sum_p a_{lp} T_p[d]  -  sum_j g_ij[d]^2 )
//   T_p[d]   = sum_{|alpha|=p} w_alpha (sum_j g_ij[d] u_j^alpha)^2
//
// Kernel 1 (edge): thread per (atom, neighbor) edge — 200K threads, no
//   barriers, no idle lanes. Writes per-atom 560-float scratch block:
//     [0:160)    G[d][j]            (g transposed: consumer reads float4s)
//     [160:480)  M4[j][grp] float4  (4 group monomials per edge)
//     [480:560)  M5[j][grp]         (5th monomial per group)
// Kernel 2 (atom): warp per atom, lane = d*4+grp. No smem, no syncwarp.
//   45 independent L2 loads per lane (fully unrolled -> high MLP), moment
//   accumulation, weighted squares, 8-shfl butterfly, coalesced store.

#define MAXN 10000
#define BLK_ATOM 560   // floats per atom scratch block

__device__ __align__(16) float g_scratch[MAXN * BLK_ATOM];

__constant__ float4 WSEL[20] = {
    {1.f,0.f,0.f,0.f},                                          // 1
    {0.f,1.f,0.f,0.f},{0.f,1.f,0.f,0.f},{0.f,1.f,0.f,0.f},     // x y z
    {0.f,0.f,1.f,0.f},{0.f,0.f,1.f,0.f},{0.f,0.f,1.f,0.f},     // x2(grp0-m5) y2 z2
    {0.f,0.f,2.f,0.f},{0.f,0.f,2.f,0.f},{0.f,0.f,2.f,0.f},     // xy xz yz
    {0.f,0.f,0.f,1.f},{0.f,0.f,0.f,1.f},{0.f,0.f,0.f,1.f},     // x3 y3 z3
    {0.f,0.f,0.f,3.f},{0.f,0.f,0.f,3.f},{0.f,0.f,0.f,3.f},     // x2y x2z y2x
    {0.f,0.f,0.f,3.f},{0.f,0.f,0.f,3.f},{0.f,0.f,0.f,3.f},     // y2z z2x z2y
    {0.f,0.f,0.f,6.f}                                           // xyz
};
__constant__ float4 ACOEF[4] = {
    { 1.0f,  0.0f, 0.0f, 0.0f},   // P0
    { 0.0f,  1.0f, 0.0f, 0.0f},   // P1
    {-0.5f,  0.0f, 1.5f, 0.0f},   // P2
    { 0.0f, -1.5f, 0.0f, 2.5f}    // P3
};

__global__ __launch_bounds__(256) void edge_kernel(
    const int*   __restrict__ types,
    const float* __restrict__ pos,
    const int*   __restrict__ nbr,
    const float* __restrict__ ctab,
    int nedges)
{
    const unsigned e = blockIdx.x * 256u + threadIdx.x;
    if (e >= (unsigned)nedges) return;
    const unsigned atom = e / 20u;
    const unsigned j    = e - atom * 20u;

    const int n = nbr[e];
    const float dx = pos[n * 3 + 0] - pos[atom * 3 + 0];
    const float dy = pos[n * 3 + 1] - pos[atom * 3 + 1];
    const float dz = pos[n * 3 + 2] - pos[atom * 3 + 2];
    const float r2 = dx * dx + dy * dy + dz * dz;
    const float rinv = rsqrtf(r2);
    const float r  = r2 * rinv;

    // Chebyshev radial basis * 0.5*fc  (rc = 5)
    const float fc = (r < 5.0f) ? fmaf(0.5f, __cosf(r * 0.6283185307179586f), 0.5f)
                                : 0.0f;
    const float xr = fmaf(r, 0.2f, -1.0f);
    const float xx = fmaf(2.0f * xr, xr, -1.0f);
    const float h  = 0.5f * fc;

    float f[8];
    {
        float tp = 1.0f, tc = xx;
        f[0] = (tp + 1.0f) * h;
        f[1] = (tc + 1.0f) * h;
        #pragma unroll
        for (int k = 2; k < 8; k++) {
            const float tn = fmaf(2.0f * xx, tc, -tp);
            f[k] = (tn + 1.0f) * h;
            tp = tc; tc = tn;
        }
    }

    const int ti = types[atom];
    const int tj = types[n];
    const float4* c4 = reinterpret_cast<const float4*>(ctab + (ti * 4 + tj) * 64);

    float* B = g_scratch + atom * BLK_ATOM;
    #pragma unroll
    for (int d = 0; d < 8; d++) {
        const float4 a = c4[d * 2 + 0];
        const float4 b = c4[d * 2 + 1];
        B[d * 20 + j] = a.x * f[0] + a.y * f[1] + a.z * f[2] + a.w * f[3]
                      + b.x * f[4] + b.y * f[5] + b.z * f[6] + b.w * f[7];
    }

    const float x = dx * rinv, y = dy * rinv, z = dz * rinv;
    const float x2 = x * x, y2 = y * y, z2 = z * z;
    const float xy = x * y, xz = x * z, yz = y * z;

    float4* M4 = reinterpret_cast<float4*>(B + 160) + j * 4;
    M4[0] = make_float4(1.0f,   x,      y,      z);        // grp0
    M4[1] = make_float4(y2,     z2,     xy,     xz);       // grp1
    M4[2] = make_float4(x2 * x, y2 * y, z2 * z, x2 * y);   // grp2
    M4[3] = make_float4(y2 * x, y2 * z, z2 * x, z2 * y);   // grp3
    reinterpret_cast<float4*>(B + 480)[j] =
             make_float4(x2,    yz,     x2 * z, xy * z);   // 5th monomials
}

__global__ __launch_bounds__(256) void atom_kernel(
    float* __restrict__ out,
    int natoms)
{
    const int warp = threadIdx.x >> 5;
    const int lane = threadIdx.x & 31;
    const int atom = blockIdx.x * 8 + warp;
    if (atom >= natoms) return;

    const int d   = lane >> 2;
    const int grp = lane & 3;
    const float* B = g_scratch + atom * BLK_ATOM;

    // g for this d: 20 contiguous floats = 5 float4 (broadcast within d-group)
    float4 gv[5];
    const float4* Gp = reinterpret_cast<const float4*>(B + d * 20);
    #pragma unroll
    for (int t = 0; t < 5; t++) gv[t] = Gp[t];
    const float* gs = reinterpret_cast<const float*>(gv);

    const float4* M4 = reinterpret_cast<const float4*>(B + 160);
    const float*  M5 = B + 480 + grp;

    float M0 = 0.f, M1 = 0.f, M2 = 0.f, M3 = 0.f, M4a = 0.f, D = 0.f;
    #pragma unroll
    for (int j = 0; j < 20; j++) {
        const float  g = gs[j];
        const float4 m = M4[j * 4 + grp];
        const float  m5 = M5[j * 4];
        D   = fmaf(g, g,   D);
        M0  = fmaf(g, m.x, M0);
        M1  = fmaf(g, m.y, M1);
        M2  = fmaf(g, m.z, M2);
        M3  = fmaf(g, m.w, M3);
        M4a = fmaf(g, m5,  M4a);
    }

    // weighted squares into T buckets
    float T0 = 0.f, T1 = 0.f, T2 = 0.f, T3 = 0.f;
    {
        const float4* W = WSEL + grp * 5;
        float s; float4 w;
        s = M0 * M0;  w = W[0];
        T0 = fmaf(s, w.x, T0); T1 = fmaf(s, w.y, T1); T2 = fmaf(s, w.z, T2); T3 = fmaf(s, w.w, T3);
        s = M1 * M1;  w = W[1];
        T0 = fmaf(s, w.x, T0); T1 = fmaf(s, w.y, T1); T2 = fmaf(s, w.z, T2); T3 = fmaf(s, w.w, T3);
        s = M2 * M2;  w = W[2];
        T0 = fmaf(s, w.x, T0); T1 = fmaf(s, w.y, T1); T2 = fmaf(s, w.z, T2); T3 = fmaf(s, w.w, T3);
        s = M3 * M3;  w = W[3];
        T0 = fmaf(s, w.x, T0); T1 = fmaf(s, w.y, T1); T2 = fmaf(s, w.z, T2); T3 = fmaf(s, w.w, T3);
        s = M4a * M4a; w = W[4];
        T0 = fmaf(s, w.x, T0); T1 = fmaf(s, w.y, T1); T2 = fmaf(s, w.z, T2); T3 = fmaf(s, w.w, T3);
    }

    // butterfly over the 4-lane d-group: every lane gets full T0..T3
    T0 += __shfl_xor_sync(0xffffffffu, T0, 1);
    T0 += __shfl_xor_sync(0xffffffffu, T0, 2);
    T1 += __shfl_xor_sync(0xffffffffu, T1, 1);
    T1 += __shfl_xor_sync(0xffffffffu, T1, 2);
    T2 += __shfl_xor_sync(0xffffffffu, T2, 1);
    T2 += __shfl_xor_sync(0xffffffffu, T2, 2);
    T3 += __shfl_xor_sync(0xffffffffu, T3, 1);
    T3 += __shfl_xor_sync(0xffffffffu, T3, 2);

    const float4 a = ACOEF[grp];
    float q = a.x * T0;
    q = fmaf(a.y, T1, q);
    q = fmaf(a.z, T2, q);
    q = fmaf(a.w, T3, q);
    out[atom * 32 + lane] = 0.5f * (q - D);
}

extern "C" void kernel_launch(void* const* d_in, const int* in_sizes, int n_in,
                              void* d_out, int out_size) {
    const int*   types = (const int*)  d_in[0];
    const float* pos   = (const float*)d_in[1];
    const int*   nbrs  = (const int*)  d_in[2];
    const float* ctab  = (const float*)d_in[3];
    float*       out   = (float*)      d_out;

    int natoms = in_sizes[0];
    if (natoms > MAXN) natoms = MAXN;
    const int nedges = natoms * 20;

    edge_kernel<<<(nedges + 255) / 256, 256>>>(types, pos, nbrs, ctab, nedges);
    atom_kernel<<<(natoms + 7) / 8, 256>>>(out, natoms);
}

// round 10
// speedup vs baseline: 1.3895x; 1.3895x over previous
#include <cuda_runtime.h>
#include <cuda_bf16.h>

// AngularDescriptor via moment expansion (fused, one warp per atom):
//   q[i,d,l] = 0.5 * ( sum_p a_{lp} T_p[d]  -  sum_j g_ij[d]^2 )
//   T_p[d]   = sum_{|alpha|=p} w_alpha (sum_j g_ij[d] u_j^alpha)^2
// Grid 1250 x 8 warps = 10000 warps (one per atom) for max concurrency.
// Phase 1: lanes 0..19 build per-neighbor g[8] + 20 unit-vector monomials,
//          written with 7 STS.128 (row stride 28 floats, 16B aligned).
// Phase 2: lane = d*4+grp accumulates 5 moments; 3 LDS + 6 FMA per neighbor.
// Epilogue: weighted squares, 8-shfl butterfly over 4-lane d-group, store.

#define WPB 8

__constant__ float4 WSEL[20] = {
    {1.f,0.f,0.f,0.f},                                          // 1
    {0.f,1.f,0.f,0.f},{0.f,1.f,0.f,0.f},{0.f,1.f,0.f,0.f},     // x y z
    {0.f,0.f,1.f,0.f},{0.f,0.f,1.f,0.f},{0.f,0.f,1.f,0.f},     // y2 z2 ... (per-grp slots)
    {0.f,0.f,2.f,0.f},{0.f,0.f,2.f,0.f},{0.f,0.f,2.f,0.f},     // xy xz yz
    {0.f,0.f,0.f,1.f},{0.f,0.f,0.f,1.f},{0.f,0.f,0.f,1.f},     // x3 y3 z3
    {0.f,0.f,0.f,3.f},{0.f,0.f,0.f,3.f},{0.f,0.f,0.f,3.f},     // x2y x2z y2x
    {0.f,0.f,0.f,3.f},{0.f,0.f,0.f,3.f},{0.f,0.f,0.f,3.f},     // y2z z2x z2y
    {0.f,0.f,0.f,6.f}                                           // xyz
};
__constant__ float4 ACOEF[4] = {
    { 1.0f,  0.0f, 0.0f, 0.0f},   // P0
    { 0.0f,  1.0f, 0.0f, 0.0f},   // P1
    {-0.5f,  0.0f, 1.5f, 0.0f},   // P2
    { 0.0f, -1.5f, 0.0f, 2.5f}    // P3
};

__global__ __launch_bounds__(WPB * 32, 6) void ang_kernel(
    const int*   __restrict__ types,
    const float* __restrict__ pos,
    const int*   __restrict__ nbr,
    const float* __restrict__ ctab,
    float*       __restrict__ out,
    int natoms)
{
    // per-neighbor row, stride 28 floats (112B):
    // [0:8) g[8] | [8+4*grp : 12+4*grp) grp monomial block | [24:28) 5th monomials
    __shared__ __align__(16) float sh[WPB][20 * 28];
    const int warp = threadIdx.x >> 5;
    const int lane = threadIdx.x & 31;
    const int atom = blockIdx.x * WPB + warp;
    if (atom >= natoms) return;
    float* S = sh[warp];

    // ---- Phase 1: per-neighbor g[8] + monomials (lanes 0..19) ----
    if (lane < 20) {
        const int n = nbr[atom * 20 + lane];          // issue gather early
        const int   ti  = types[atom];
        const float pix = pos[atom * 3 + 0];
        const float piy = pos[atom * 3 + 1];
        const float piz = pos[atom * 3 + 2];

        const float dx = pos[n * 3 + 0] - pix;
        const float dy = pos[n * 3 + 1] - piy;
        const float dz = pos[n * 3 + 2] - piz;
        const int tj = types[n];

        const float r2 = dx * dx + dy * dy + dz * dz;
        const float rinv = rsqrtf(r2);
        const float r  = r2 * rinv;

        const float fc = (r < 5.0f) ? fmaf(0.5f, __cosf(r * 0.6283185307179586f), 0.5f)
                                    : 0.0f;
        const float xr = fmaf(r, 0.2f, -1.0f);
        const float xx = fmaf(2.0f * xr, xr, -1.0f);
        const float h  = 0.5f * fc;

        float f[8];
        {
            float tp = 1.0f, tc = xx;
            f[0] = (tp + 1.0f) * h;
            f[1] = (tc + 1.0f) * h;
            #pragma unroll
            for (int k = 2; k < 8; k++) {
                const float tn = fmaf(2.0f * xx, tc, -tp);
                f[k] = (tn + 1.0f) * h;
                tp = tc; tc = tn;
            }
        }

        const float4* c4 = reinterpret_cast<const float4*>(ctab + (ti * 4 + tj) * 64);
        float g[8];
        #pragma unroll
        for (int dd = 0; dd < 8; dd++) {
            const float4 a = c4[dd * 2 + 0];
            const float4 b = c4[dd * 2 + 1];
            g[dd] = a.x * f[0] + a.y * f[1] + a.z * f[2] + a.w * f[3]
                  + b.x * f[4] + b.y * f[5] + b.z * f[6] + b.w * f[7];
        }

        const float x = dx * rinv, y = dy * rinv, z = dz * rinv;
        const float x2 = x * x, y2 = y * y, z2 = z * z;
        const float xy = x * y, xz = x * z, yz = y * z;

        float4* R = reinterpret_cast<float4*>(S + lane * 28);
        R[0] = make_float4(g[0], g[1], g[2], g[3]);
        R[1] = make_float4(g[4], g[5], g[6], g[7]);
        R[2] = make_float4(1.0f,     x,       y,       z);       // grp0 block
        R[3] = make_float4(y2,       z2,      xy,      xz);      // grp1 block
        R[4] = make_float4(x2 * x,   y2 * y,  z2 * z,  x2 * y);  // grp2 block
        R[5] = make_float4(y2 * x,   y2 * z,  z2 * x,  z2 * y);  // grp3 block
        R[6] = make_float4(x2,       yz,      x2 * z,  xy * z);  // 5th monomials
    }
    __syncwarp();

    // ---- Phase 2: moment accumulation (3 LDS + 6 FMA per neighbor) ----
    const int d   = lane >> 2;
    const int grp = lane & 3;
    const float* Rg  = S + d;
    const float* Rm4 = S + 8 + 4 * grp;
    const float* Rm5 = S + 24 + grp;

    float M0 = 0.f, M1 = 0.f, M2 = 0.f, M3 = 0.f, M4 = 0.f, D = 0.f;
    #pragma unroll
    for (int j = 0; j < 20; j++) {
        const float  g  = Rg[j * 28];
        const float4 m4 = *reinterpret_cast<const float4*>(Rm4 + j * 28);
        const float  m5 = Rm5[j * 28];
        D  = fmaf(g, g,    D);
        M0 = fmaf(g, m4.x, M0);
        M1 = fmaf(g, m4.y, M1);
        M2 = fmaf(g, m4.z, M2);
        M3 = fmaf(g, m4.w, M3);
        M4 = fmaf(g, m5,   M4);
    }

    // ---- Epilogue: weighted squares into T buckets ----
    float T0 = 0.f, T1 = 0.f, T2 = 0.f, T3 = 0.f;
    {
        const float4* W = WSEL + grp * 5;
        float s; float4 w;
        s = M0 * M0; w = W[0];
        T0 = fmaf(s, w.x, T0); T1 = fmaf(s, w.y, T1); T2 = fmaf(s, w.z, T2); T3 = fmaf(s, w.w, T3);
        s = M1 * M1; w = W[1];
        T0 = fmaf(s, w.x, T0); T1 = fmaf(s, w.y, T1); T2 = fmaf(s, w.z, T2); T3 = fmaf(s, w.w, T3);
        s = M2 * M2; w = W[2];
        T0 = fmaf(s, w.x, T0); T1 = fmaf(s, w.y, T1); T2 = fmaf(s, w.z, T2); T3 = fmaf(s, w.w, T3);
        s = M3 * M3; w = W[3];
        T0 = fmaf(s, w.x, T0); T1 = fmaf(s, w.y, T1); T2 = fmaf(s, w.z, T2); T3 = fmaf(s, w.w, T3);
        s = M4 * M4; w = W[4];
        T0 = fmaf(s, w.x, T0); T1 = fmaf(s, w.y, T1); T2 = fmaf(s, w.z, T2); T3 = fmaf(s, w.w, T3);
    }

    // butterfly over the 4-lane d-group
    T0 += __shfl_xor_sync(0xffffffffu, T0, 1);
    T0 += __shfl_xor_sync(0xffffffffu, T0, 2);
    T1 += __shfl_xor_sync(0xffffffffu, T1, 1);
    T1 += __shfl_xor_sync(0xffffffffu, T1, 2);
    T2 += __shfl_xor_sync(0xffffffffu, T2, 1);
    T2 += __shfl_xor_sync(0xffffffffu, T2, 2);
    T3 += __shfl_xor_sync(0xffffffffu, T3, 1);
    T3 += __shfl_xor_sync(0xffffffffu, T3, 2);

    const float4 a = ACOEF[grp];
    float q = a.x * T0;
    q = fmaf(a.y, T1, q);
    q = fmaf(a.z, T2, q);
    q = fmaf(a.w, T3, q);
    out[atom * 32 + lane] = 0.5f * (q - D);
}

extern "C" void kernel_launch(void* const* d_in, const int* in_sizes, int n_in,
                              void* d_out, int out_size) {
    const int*   types = (const int*)  d_in[0];
    const float* pos   = (const float*)d_in[1];
    const int*   nbrs  = (const int*)  d_in[2];
    const float* ctab  = (const float*)d_in[3];
    float*       out   = (float*)      d_out;

    const int natoms = in_sizes[0];
    const int blocks = (natoms + WPB - 1) / WPB;
    ang_kernel<<<blocks, WPB * 32>>>(types, pos, nbrs, ctab, out, natoms);
}

// round 11
// speedup vs baseline: 1.5606x; 1.1231x over previous
#include <cuda_runtime.h>
#include <cuda_bf16.h>

// AngularDescriptor via moment expansion (fused, one warp per atom).
// R11: gather-wavefront reduction.
//  - pack_kernel: posw[i] = (x,y,z, bitcast(type)) -> one LDG.128 per edge gather.
//  - c_table staged into padded shared (stride 68 floats -> 4 tj rows hit
//    distinct bank groups, conflict-free) replacing 4-line LDG wavefronts.
// Phase 1: lanes 0..19: per-neighbor g[8] + 20 unit-vector monomials, 7 STS.128.
// Phase 2: lane = d*4+grp: 5 moments, 3 LDS + 6 FMA per neighbor.
// Epilogue: weighted squares, 8-shfl butterfly, coalesced store.

#define WPB 8
#define MAXN 10000

__device__ __align__(16) float4 g_posw[MAXN];

__constant__ float4 WSEL[20] = {
    {1.f,0.f,0.f,0.f},
    {0.f,1.f,0.f,0.f},{0.f,1.f,0.f,0.f},{0.f,1.f,0.f,0.f},
    {0.f,0.f,1.f,0.f},{0.f,0.f,1.f,0.f},{0.f,0.f,1.f,0.f},
    {0.f,0.f,2.f,0.f},{0.f,0.f,2.f,0.f},{0.f,0.f,2.f,0.f},
    {0.f,0.f,0.f,1.f},{0.f,0.f,0.f,1.f},{0.f,0.f,0.f,1.f},
    {0.f,0.f,0.f,3.f},{0.f,0.f,0.f,3.f},{0.f,0.f,0.f,3.f},
    {0.f,0.f,0.f,3.f},{0.f,0.f,0.f,3.f},{0.f,0.f,0.f,3.f},
    {0.f,0.f,0.f,6.f}
};
__constant__ float4 ACOEF[4] = {
    { 1.0f,  0.0f, 0.0f, 0.0f},
    { 0.0f,  1.0f, 0.0f, 0.0f},
    {-0.5f,  0.0f, 1.5f, 0.0f},
    { 0.0f, -1.5f, 0.0f, 2.5f}
};

__global__ __launch_bounds__(256) void pack_kernel(
    const int* __restrict__ types,
    const float* __restrict__ pos,
    int n)
{
    const int i = blockIdx.x * 256 + threadIdx.x;
    if (i < n) {
        g_posw[i] = make_float4(pos[i * 3 + 0], pos[i * 3 + 1], pos[i * 3 + 2],
                                __int_as_float(types[i]));
    }
}

__global__ __launch_bounds__(WPB * 32, 6) void ang_kernel(
    const int*   __restrict__ nbr,
    const float* __restrict__ ctab,
    float*       __restrict__ out,
    int natoms)
{
    // per-neighbor row, stride 28 floats:
    // [0:8) g[8] | [8+4*grp : 12+4*grp) grp monomial block | [24:28) 5th monomials
    __shared__ __align__(16) float sh[WPB][20 * 28];
    __shared__ __align__(16) float cs[16 * 68];   // c_table, padded rows
    const int warp = threadIdx.x >> 5;
    const int lane = threadIdx.x & 31;
    const int atom = blockIdx.x * WPB + warp;

    // stage c_table (1024 floats) into padded smem
    #pragma unroll
    for (int t = threadIdx.x; t < 1024; t += WPB * 32) {
        const int row = t >> 6, col = t & 63;
        cs[row * 68 + col] = ctab[t];
    }
    __syncthreads();

    if (atom >= natoms) return;
    float* S = sh[warp];

    // ---- Phase 1: per-neighbor g[8] + monomials (lanes 0..19) ----
    if (lane < 20) {
        const int n = nbr[atom * 20 + lane];
        const float4 pn = g_posw[n];
        const float4 pa = g_posw[atom];
        const int ti = __float_as_int(pa.w);
        const int tj = __float_as_int(pn.w);

        const float dx = pn.x - pa.x;
        const float dy = pn.y - pa.y;
        const float dz = pn.z - pa.z;

        const float r2 = dx * dx + dy * dy + dz * dz;
        const float rinv = rsqrtf(r2);
        const float r  = r2 * rinv;

        const float fc = (r < 5.0f) ? fmaf(0.5f, __cosf(r * 0.6283185307179586f), 0.5f)
                                    : 0.0f;
        const float xr = fmaf(r, 0.2f, -1.0f);
        const float xx = fmaf(2.0f * xr, xr, -1.0f);
        const float h  = 0.5f * fc;

        float f[8];
        {
            float tp = 1.0f, tc = xx;
            f[0] = (tp + 1.0f) * h;
            f[1] = (tc + 1.0f) * h;
            #pragma unroll
            for (int k = 2; k < 8; k++) {
                const float tn = fmaf(2.0f * xx, tc, -tp);
                f[k] = (tn + 1.0f) * h;
                tp = tc; tc = tn;
            }
        }

        const float4* c4 = reinterpret_cast<const float4*>(cs + (ti * 4 + tj) * 68);
        float g[8];
        #pragma unroll
        for (int dd = 0; dd < 8; dd++) {
            const float4 a = c4[dd * 2 + 0];
            const float4 b = c4[dd * 2 + 1];
            g[dd] = a.x * f[0] + a.y * f[1] + a.z * f[2] + a.w * f[3]
                  + b.x * f[4] + b.y * f[5] + b.z * f[6] + b.w * f[7];
        }

        const float x = dx * rinv, y = dy * rinv, z = dz * rinv;
        const float x2 = x * x, y2 = y * y, z2 = z * z;
        const float xy = x * y, xz = x * z, yz = y * z;

        float4* R = reinterpret_cast<float4*>(S + lane * 28);
        R[0] = make_float4(g[0], g[1], g[2], g[3]);
        R[1] = make_float4(g[4], g[5], g[6], g[7]);
        R[2] = make_float4(1.0f,     x,       y,       z);       // grp0 block
        R[3] = make_float4(y2,       z2,      xy,      xz);      // grp1 block
        R[4] = make_float4(x2 * x,   y2 * y,  z2 * z,  x2 * y);  // grp2 block
        R[5] = make_float4(y2 * x,   y2 * z,  z2 * x,  z2 * y);  // grp3 block
        R[6] = make_float4(x2,       yz,      x2 * z,  xy * z);  // 5th monomials
    }
    __syncwarp();

    // ---- Phase 2: moment accumulation (3 LDS + 6 FMA per neighbor) ----
    const int d   = lane >> 2;
    const int grp = lane & 3;
    const float* Rg  = S + d;
    const float* Rm4 = S + 8 + 4 * grp;
    const float* Rm5 = S + 24 + grp;

    float M0 = 0.f, M1 = 0.f, M2 = 0.f, M3 = 0.f, M4 = 0.f, D = 0.f;
    #pragma unroll
    for (int j = 0; j < 20; j++) {
        const float  g  = Rg[j * 28];
        const float4 m4 = *reinterpret_cast<const float4*>(Rm4 + j * 28);
        const float  m5 = Rm5[j * 28];
        D  = fmaf(g, g,    D);
        M0 = fmaf(g, m4.x, M0);
        M1 = fmaf(g, m4.y, M1);
        M2 = fmaf(g, m4.z, M2);
        M3 = fmaf(g, m4.w, M3);
        M4 = fmaf(g, m5,   M4);
    }

    // ---- Epilogue: weighted squares into T buckets ----
    float T0 = 0.f, T1 = 0.f, T2 = 0.f, T3 = 0.f;
    {
        const float4* W = WSEL + grp * 5;
        float s; float4 w;
        s = M0 * M0; w = W[0];
        T0 = fmaf(s, w.x, T0); T1 = fmaf(s, w.y, T1); T2 = fmaf(s, w.z, T2); T3 = fmaf(s, w.w, T3);
        s = M1 * M1; w = W[1];
        T0 = fmaf(s, w.x, T0); T1 = fmaf(s, w.y, T1); T2 = fmaf(s, w.z, T2); T3 = fmaf(s, w.w, T3);
        s = M2 * M2; w = W[2];
        T0 = fmaf(s, w.x, T0); T1 = fmaf(s, w.y, T1); T2 = fmaf(s, w.z, T2); T3 = fmaf(s, w.w, T3);
        s = M3 * M3; w = W[3];
        T0 = fmaf(s, w.x, T0); T1 = fmaf(s, w.y, T1); T2 = fmaf(s, w.z, T2); T3 = fmaf(s, w.w, T3);
        s = M4 * M4; w = W[4];
        T0 = fmaf(s, w.x, T0); T1 = fmaf(s, w.y, T1); T2 = fmaf(s, w.z, T2); T3 = fmaf(s, w.w, T3);
    }

    // butterfly over the 4-lane d-group
    T0 += __shfl_xor_sync(0xffffffffu, T0, 1);
    T0 += __shfl_xor_sync(0xffffffffu, T0, 2);
    T1 += __shfl_xor_sync(0xffffffffu, T1, 1);
    T1 += __shfl_xor_sync(0xffffffffu, T1, 2);
    T2 += __shfl_xor_sync(0xffffffffu, T2, 1);
    T2 += __shfl_xor_sync(0xffffffffu, T2, 2);
    T3 += __shfl_xor_sync(0xffffffffu, T3, 1);
    T3 += __shfl_xor_sync(0xffffffffu, T3, 2);

    const float4 a = ACOEF[grp];
    float q = a.x * T0;
    q = fmaf(a.y, T1, q);
    q = fmaf(a.z, T2, q);
    q = fmaf(a.w, T3, q);
    out[atom * 32 + lane] = 0.5f * (q - D);
}

extern "C" void kernel_launch(void* const* d_in, const int* in_sizes, int n_in,
                              void* d_out, int out_size) {
    const int*   types = (const int*)  d_in[0];
    const float* pos   = (const float*)d_in[1];
    const int*   nbrs  = (const int*)  d_in[2];
    const float* ctab  = (const float*)d_in[3];
    float*       out   = (float*)      d_out;

    int natoms = in_sizes[0];
    if (natoms > MAXN) natoms = MAXN;

    pack_kernel<<<(natoms + 255) / 256, 256>>>(types, pos, natoms);
    ang_kernel<<<(natoms + WPB - 1) / WPB, WPB * 32>>>(nbrs, ctab, out, natoms);
}